// round 9
// baseline (speedup 1.0000x reference)
#include <cuda_runtime.h>
#include <cstdint>
#include <cfloat>

// Shapes fixed by the problem: x is (64, 128, 4096) fp32.
#define NPOS   4096
#define NROWS  8192          // 64*128
#define NTILES 33            // tiles of 124 centers (last: 126)
#define NSTRIP 32            // 8192 rows / 256 rows-per-strip
#define RMAX   512           // gaussian radius cap (R=28 for width 3)
#define GRID   296           // 148 SMs x 2 resident blocks (guaranteed)
#define BLK    512

// Scratch in __device__ globals (no allocations allowed).
__device__ unsigned int g_part[NSTRIP * NPOS]; // per-strip packed counts
__device__ float        g_vec[NPOS];
__device__ int          g_min_bits;            // nonneg floats: int cmp == float cmp
__device__ int          g_max_bits;
__device__ unsigned int g_bar_cnt;             // software grid barrier
__device__ unsigned int g_bar_gen;             // monotonic across replays

// Grid-wide barrier. Generation-snapshot style: no reset needed across graph
// replays (gen is monotonic; cnt self-resets each episode). All GRID blocks
// are co-resident by construction (__launch_bounds__(BLK, 2), grid=296).
__device__ __forceinline__ void gbar() {
    __threadfence();
    __syncthreads();
    if (threadIdx.x == 0) {
        unsigned g = *((volatile unsigned int*)&g_bar_gen);
        if (atomicAdd(&g_bar_cnt, 1u) == GRID - 1u) {
            atomicExch(&g_bar_cnt, 0u);
            __threadfence();
            atomicAdd(&g_bar_gen, 1u);
        } else {
            while (*((volatile unsigned int*)&g_bar_gen) == g) { __nanosleep(64); }
        }
        __threadfence();
    }
    __syncthreads();
}

// ---------------------------------------------------------------------------
// Single persistent kernel: counts -> [grid barrier] -> vec -> [grid barrier]
// -> broadcast. Eliminates two kernel-boundary bubbles.
// ---------------------------------------------------------------------------
__global__ __launch_bounds__(BLK, 2) void k_fused(const float* __restrict__ x,
                                                  const float* __restrict__ lpw,
                                                  const float* __restrict__ lvw,
                                                  float* __restrict__ out) {
    __shared__ unsigned int scol[128];
    __shared__ unsigned int scnt[128 + 2 * RMAX];
    __shared__ float sgp[RMAX + 1];
    __shared__ float sgv[RMAX + 1];
    __shared__ float smn[4], smx[4];

    const int tid  = threadIdx.x;
    const int lane = tid & 31;
    const int warp = tid >> 5;                 // 0..15

    if (blockIdx.x == 0 && tid == 0) {
        g_min_bits = 0x7F800000;               // +inf (values are >= 0)
        g_max_bits = 0;
    }

    // ---------------- Phase 1: counts (R4-proven float4 body) ----------------
    // Work item = (strip, tile): 256 rows x 128-col warp tile, 16 warps x 16
    // rows. dd matches reference exactly: (x[p+1]-x[p]) - (x[p]-x[p-1]).
    if (tid < 128) scol[tid] = 0u;
    __syncthreads();

    for (int item = blockIdx.x; item < NTILES * NSTRIP; item += GRID) {
        const int tile = item % NTILES;
        const int strip = item / NTILES;
        const int s    = tile * 124;
        const int cmax = (tile == NTILES - 1) ? (NPOS - 2) : (s + 124);
        const int p0   = s + 4 * lane + 1;

        unsigned p0c = 0, p1c = 0, p2c = 0, p3c = 0;
        unsigned v0c = 0, v1c = 0, v2c = 0, v3c = 0;

        const float* xb = x + (size_t)(strip * 256 + warp * 16) * NPOS + s;

        #pragma unroll 4
        for (int k = 0; k < 16; k++) {
            float4 v = __ldcs((const float4*)(xb + (size_t)k * NPOS) + lane);
            float xn0 = __shfl_down_sync(0xFFFFFFFFu, v.x, 1);
            float xn1 = __shfl_down_sync(0xFFFFFFFFu, v.y, 1);

            float d0 = v.y - v.x;
            float d1 = v.z - v.y;
            float d2 = v.w - v.z;
            float d3 = xn0 - v.w;
            float d4 = xn1 - xn0;

            float dd0 = d1 - d0;
            float dd1 = d2 - d1;
            float dd2 = d3 - d2;
            float dd3 = d4 - d3;

            p0c += (dd0 < 0.0f); v0c += (dd0 > 0.0f);
            p1c += (dd1 < 0.0f); v1c += (dd1 > 0.0f);
            p2c += (dd2 < 0.0f); v2c += (dd2 > 0.0f);
            p3c += (dd3 < 0.0f); v3c += (dd3 > 0.0f);
        }

        const int i0 = 4 * lane;
        if (p0 + 0 <= cmax) atomicAdd(&scol[i0 + 0], p0c | (v0c << 16));
        if (p0 + 1 <= cmax) atomicAdd(&scol[i0 + 1], p1c | (v1c << 16));
        if (p0 + 2 <= cmax) atomicAdd(&scol[i0 + 2], p2c | (v2c << 16));
        if (p0 + 3 <= cmax) atomicAdd(&scol[i0 + 3], p3c | (v3c << 16));
        __syncthreads();

        const int ncols = cmax - s;            // 124 (126 for last tile)
        if (tid < ncols) {
            g_part[strip * NPOS + (s + 1 + tid)] = scol[tid];
            scol[tid] = 0u;                    // owner-resets: no extra sync race
        } else if (tid < 128) {
            scol[tid] = 0u;
        }
        __syncthreads();
    }

    gbar();

    // ---------------- Phase 2: gaussian conv + min/max (blocks 0..31) --------
    if (blockIdx.x < NPOS / 128) {
        const float wp = expf(*lpw);
        const float wv = expf(*lvw);
        int R = (int)(9.0f * fmaxf(wp, wv)) + 1;
        if (R > RMAX) R = RMAX;

        for (int d = tid; d <= R; d += BLK) {
            float fd = (float)d;
            float tp = fd / wp;
            float tv = fd / wv;
            sgp[d] = expf(-tp * tp);
            sgv[d] = expf(-tv * tv);
        }

        const int pbase = blockIdx.x * 128;
        const int sbase = pbase - R;
        const int span  = 128 + 2 * R;
        for (int j = tid; j < span; j += BLK) {
            const int c = sbase + j;
            unsigned sum = 0;
            if (c >= 1 && c <= NPOS - 2) {
                #pragma unroll 8
                for (int k = 0; k < NSTRIP; k++) sum += g_part[k * NPOS + c];
            }
            scnt[j] = sum;
        }
        __syncthreads();

        if (tid < 128) {
            const int ci = tid + R;
            unsigned pk0 = scnt[ci];
            float acc = (float)(pk0 & 0xFFFFu) * sgp[0] + (float)(pk0 >> 16) * sgv[0];
            for (int d = 1; d <= R; d++) {
                unsigned pk = scnt[ci + d] + scnt[ci - d];
                acc += (float)(pk & 0xFFFFu) * sgp[d] + (float)(pk >> 16) * sgv[d];
            }
            g_vec[pbase + tid] = acc;

            float mn = acc, mx = acc;
            #pragma unroll
            for (int o = 16; o > 0; o >>= 1) {
                mn = fminf(mn, __shfl_xor_sync(0xFFFFFFFFu, mn, o));
                mx = fmaxf(mx, __shfl_xor_sync(0xFFFFFFFFu, mx, o));
            }
            if (lane == 0) { smn[warp] = mn; smx[warp] = mx; }
        }
        __syncthreads();
        if (tid == 0) {
            float mn = fminf(fminf(smn[0], smn[1]), fminf(smn[2], smn[3]));
            float mx = fmaxf(fmaxf(smx[0], smx[1]), fmaxf(smx[2], smx[3]));
            atomicMin(&g_min_bits, __float_as_int(mn));
            atomicMax(&g_max_bits, __float_as_int(mx));
        }
    }

    gbar();

    // ---------------- Phase 3: normalize + broadcast --------------------------
    {
        const float mn = __int_as_float(g_min_bits);
        const float inv = 1.0f / (__int_as_float(g_max_bits) - mn + 1e-6f);

        float4 a = ((const float4*)g_vec)[2 * tid];
        float4 b = ((const float4*)g_vec)[2 * tid + 1];
        a.x = (a.x - mn) * inv;  a.y = (a.y - mn) * inv;
        a.z = (a.z - mn) * inv;  a.w = (a.w - mn) * inv;
        b.x = (b.x - mn) * inv;  b.y = (b.y - mn) * inv;
        b.z = (b.z - mn) * inv;  b.w = (b.w - mn) * inv;

        float4* ob = (float4*)out + 2 * tid;
        for (int row = blockIdx.x; row < NROWS; row += GRID) {
            float4* o = ob + (size_t)row * (NPOS / 4);
            o[0] = a;
            o[1] = b;
        }
    }
}

// ---------------------------------------------------------------------------
extern "C" void kernel_launch(void* const* d_in, const int* in_sizes, int n_in,
                              void* d_out, int out_size) {
    const float* x   = (const float*)d_in[0];
    const float* lpw = (const float*)d_in[1];
    const float* lvw = (const float*)d_in[2];
    float* out = (float*)d_out;

    k_fused<<<GRID, BLK>>>(x, lpw, lvw, out);
}